// round 16
// baseline (speedup 1.0000x reference)
#include <cuda_runtime.h>
#include <math.h>

#define NJ   14
#define ELEM (NJ * 3)      // 42 floats per element per tensor
#define TPB  128
#define ROW  43            // padded smem row (gcd(43,32)=1 -> conflict-free)
#define WELEM 32           // elements per warp
#define WF4   336          // float4 per tensor per warp slab (32*42/4)

__device__ __forceinline__ float fast_sqrt(float x) {
    return x * rsqrtf(x + 1e-30f);
}

// Branchless Jacobi rotation, 2 MUFUs deep, division-free.
__device__ __forceinline__ void jacobi_rot(float A[3][3], float V[3][3], int p, int q) {
    float apq = A[p][q];
    float app = A[p][p], aqq = A[q][q];
    float h = aqq - app;
    float w = rsqrtf(h * h + 4.0f * apq * apq + 1e-38f);
    float sgn = copysignf(1.0f, h);
    float cos2t = fminf(fabsf(h) * w, 1.0f);
    float sin2t = 2.0f * apq * w * sgn;
    float c2 = 0.5f * (1.0f + cos2t);
    float invc = rsqrtf(c2);
    float c = c2 * invc;
    float s = 0.5f * sin2t * invc;
    int r = 3 - p - q;
    float arp = A[r][p], arq = A[r][q];
    float narp = c * arp - s * arq;
    float narq = s * arp + c * arq;
    A[r][p] = narp; A[p][r] = narp;
    A[r][q] = narq; A[q][r] = narq;
    float napp = c * c * app - 2.0f * s * c * apq + s * s * aqq;
    float naqq = s * s * app + 2.0f * s * c * apq + c * c * aqq;
    A[p][p] = napp; A[q][q] = naqq;
    A[p][q] = 0.0f; A[q][p] = 0.0f;
#pragma unroll
    for (int i = 0; i < 3; i++) {
        float vip = V[i][p], viq = V[i][q];
        V[i][p] = c * vip - s * viq;
        V[i][q] = s * vip + c * viq;
    }
}

__global__ void __launch_bounds__(TPB, 5)
pampjpe_kernel(const float* __restrict__ pred,
               const float* __restrict__ gt,
               float* __restrict__ out, int B)
{
    __shared__ float sp[TPB * ROW];
    __shared__ float sg[TPB * ROW];

    const int base = blockIdx.x * TPB;
    const int tid  = threadIdx.x;
    const int valid = min(TPB, B - base);

    const float* __restrict__ pbase = pred + (size_t)base * ELEM;
    const float* __restrict__ gbase = gt   + (size_t)base * ELEM;

    if (valid == TPB) {
        // Warp-autonomous staging: each warp stages its own 32 elements into
        // its own smem partition; only __syncwarp needed. Warps desynchronize.
        const int lane  = tid & 31;
        const int wbase = (tid >> 5) * WELEM;              // first element of this warp
        const float4* __restrict__ p4 = (const float4*)(pbase + (size_t)wbase * ELEM);
        const float4* __restrict__ g4 = (const float4*)(gbase + (size_t)wbase * ELEM);
        float* __restrict__ wsp = &sp[wbase * ROW];
        float* __restrict__ wsg = &sg[wbase * ROW];

#pragma unroll 3
        for (int i4 = lane; i4 < WF4; i4 += 32) {
            float4 vp = p4[i4];
            float4 vg = g4[i4];
            int idx = i4 * 4;
            float ap[4] = {vp.x, vp.y, vp.z, vp.w};
            float ag[4] = {vg.x, vg.y, vg.z, vg.w};
#pragma unroll
            for (int c = 0; c < 4; c++) {
                int id = idx + c;
                int e = id / ELEM;          // local element 0..31
                int k = id - e * ELEM;
                wsp[e * ROW + k] = ap[c];
                wsg[e * ROW + k] = ag[c];
            }
        }
        __syncwarp();
    } else {
        const int total = valid * ELEM;
        for (int i = tid; i < total; i += TPB) {
            int e = i / ELEM;
            int k = i - e * ELEM;
            sp[e * ROW + k] = pbase[i];
            sg[e * ROW + k] = gbase[i];
        }
        __syncthreads();
    }

    if (tid >= valid) return;

    const float* P = &sp[tid * ROW];
    const float* G = &sg[tid * ROW];

    // Means
    float mu1[3] = {0.f, 0.f, 0.f};
    float mu2[3] = {0.f, 0.f, 0.f};
#pragma unroll
    for (int j = 0; j < NJ; j++) {
#pragma unroll
        for (int a = 0; a < 3; a++) {
            mu1[a] += P[j * 3 + a];
            mu2[a] += G[j * 3 + a];
        }
    }
    const float invJ = 1.0f / (float)NJ;
#pragma unroll
    for (int a = 0; a < 3; a++) { mu1[a] *= invJ; mu2[a] *= invJ; }

    // Cross-covariance K[a][b] = sum_j x_j[a]*y_j[b]; var1 = sum |x|^2
    float K[3][3] = {{0}};
    float var1 = 0.f;
#pragma unroll
    for (int j = 0; j < NJ; j++) {
        float x[3], y[3];
#pragma unroll
        for (int a = 0; a < 3; a++) {
            x[a] = P[j * 3 + a] - mu1[a];
            y[a] = G[j * 3 + a] - mu2[a];
            var1 += x[a] * x[a];
        }
#pragma unroll
        for (int a = 0; a < 3; a++)
#pragma unroll
            for (int b = 0; b < 3; b++)
                K[a][b] += x[a] * y[b];
    }

    // A = K^T K (symmetric)
    float A[3][3];
#pragma unroll
    for (int i = 0; i < 3; i++)
#pragma unroll
        for (int j = i; j < 3; j++) {
            float acc = 0.f;
#pragma unroll
            for (int k2 = 0; k2 < 3; k2++) acc += K[k2][i] * K[k2][j];
            A[i][j] = acc; A[j][i] = acc;
        }

    // Jacobi eigen-decomposition: 2 cyclic sweeps + (0,1) touch-up = 7 rotations
    float V[3][3] = {{1.f, 0.f, 0.f}, {0.f, 1.f, 0.f}, {0.f, 0.f, 1.f}};
#pragma unroll
    for (int sweep = 0; sweep < 2; sweep++) {
        jacobi_rot(A, V, 0, 1);
        jacobi_rot(A, V, 0, 2);
        jacobi_rot(A, V, 1, 2);
    }
    jacobi_rot(A, V, 0, 1);

    float lam[3] = {A[0][0], A[1][1], A[2][2]};
    // Sort eigenpairs descending
#pragma unroll
    for (int a = 0; a < 2; a++)
#pragma unroll
        for (int b = a + 1; b < 3; b++)
            if (lam[a] < lam[b]) {
                float tl = lam[a]; lam[a] = lam[b]; lam[b] = tl;
#pragma unroll
                for (int r = 0; r < 3; r++) {
                    float tv = V[r][a]; V[r][a] = V[r][b]; V[r][b] = tv;
                }
            }

    // v0, v1 = top right singular vectors of K; v2 = v0 x v1 forces det(V)=+1
    float v0[3] = {V[0][0], V[1][0], V[2][0]};
    float v1[3] = {V[0][1], V[1][1], V[2][1]};
    float v2[3] = {v0[1]*v1[2] - v0[2]*v1[1],
                   v0[2]*v1[0] - v0[0]*v1[2],
                   v0[0]*v1[1] - v0[1]*v1[0]};

    // u0 = normalize(K v0); u1 = normalize(K v1 - (u0.Kv1)u0); u2 = u0 x u1
    float u0[3], u1[3];
#pragma unroll
    for (int i = 0; i < 3; i++) {
        u0[i] = K[i][0]*v0[0] + K[i][1]*v0[1] + K[i][2]*v0[2];
        u1[i] = K[i][0]*v1[0] + K[i][1]*v1[1] + K[i][2]*v1[2];
    }
    float n0 = rsqrtf(u0[0]*u0[0] + u0[1]*u0[1] + u0[2]*u0[2] + 1e-30f);
#pragma unroll
    for (int i = 0; i < 3; i++) u0[i] *= n0;
    float dot01 = u0[0]*u1[0] + u0[1]*u1[1] + u0[2]*u1[2];
#pragma unroll
    for (int i = 0; i < 3; i++) u1[i] -= dot01 * u0[i];
    float n1 = rsqrtf(u1[0]*u1[0] + u1[1]*u1[1] + u1[2]*u1[2] + 1e-30f);
#pragma unroll
    for (int i = 0; i < 3; i++) u1[i] *= n1;
    float u2[3] = {u0[1]*u1[2] - u0[2]*u1[1],
                   u0[2]*u1[0] - u0[0]*u1[2],
                   u0[0]*u1[1] - u0[1]*u1[0]};

    // R = v0 u0^T + v1 u1^T + v2 u2^T
    float R[3][3];
#pragma unroll
    for (int i = 0; i < 3; i++)
#pragma unroll
        for (int j = 0; j < 3; j++)
            R[i][j] = v0[i]*u0[j] + v1[i]*u1[j] + v2[i]*u2[j];

    // scale = trace(R K) / var1
    float trRK = 0.f;
#pragma unroll
    for (int i = 0; i < 3; i++)
#pragma unroll
        for (int k2 = 0; k2 < 3; k2++)
            trRK += R[i][k2] * K[k2][i];
    float scale = __fdividef(trRK, var1 + 1e-30f);

    // Per-joint error, averaged
    float acc = 0.f;
#pragma unroll
    for (int j = 0; j < NJ; j++) {
        float x[3], y[3];
#pragma unroll
        for (int a = 0; a < 3; a++) {
            x[a] = P[j * 3 + a] - mu1[a];
            y[a] = G[j * 3 + a] - mu2[a];
        }
        float d0 = scale * (R[0][0]*x[0] + R[0][1]*x[1] + R[0][2]*x[2]) - y[0];
        float d1 = scale * (R[1][0]*x[0] + R[1][1]*x[1] + R[1][2]*x[2]) - y[1];
        float d2 = scale * (R[2][0]*x[0] + R[2][1]*x[1] + R[2][2]*x[2]) - y[2];
        acc += fast_sqrt(d0*d0 + d1*d1 + d2*d2);
    }
    out[base + tid] = acc * invJ;
}

extern "C" void kernel_launch(void* const* d_in, const int* in_sizes, int n_in,
                              void* d_out, int out_size) {
    const float* pred = (const float*)d_in[0];
    const float* gt   = (const float*)d_in[1];
    float* out = (float*)d_out;
    int B = in_sizes[0] / ELEM;
    int grid = (B + TPB - 1) / TPB;
    pampjpe_kernel<<<grid, TPB>>>(pred, gt, out, B);
}

// round 17
// speedup vs baseline: 1.3222x; 1.3222x over previous
#include <cuda_runtime.h>
#include <math.h>
#include <stdint.h>

#define NJ    14
#define EF    42            // floats per element per tensor
#define TPB   128
#define WARPS 4
#define TILE  32            // elements per warp-tile
#define TILE_F (TILE * EF)  // 1344 floats per tensor per tile
#define TILE_F4 (TILE_F / 4)// 336 float4
#define BUF_F  (2 * TILE_F) // p then g: 2688 floats per buffer
#define GRID  296           // 2 blocks/SM * 148 SMs

__device__ __forceinline__ float fast_sqrt(float x) {
    return x * rsqrtf(x + 1e-30f);
}

__device__ __forceinline__ void cp16(uint32_t dst_smem, const void* src_gmem) {
    asm volatile("cp.async.cg.shared.global [%0], [%1], 16;\n"
                 :: "r"(dst_smem), "l"(src_gmem) : "memory");
}

__device__ __forceinline__ uint32_t smem_u32(const void* p) {
    uint32_t r;
    asm("{ .reg .u64 t; cvta.to.shared.u64 t, %1; cvt.u32.u64 %0, t; }"
        : "=r"(r) : "l"(p));
    return r;
}

// Branchless Jacobi rotation, 2 MUFUs deep, division-free. (champion-proven)
__device__ __forceinline__ void jacobi_rot(float A[3][3], float V[3][3], int p, int q) {
    float apq = A[p][q];
    float app = A[p][p], aqq = A[q][q];
    float h = aqq - app;
    float w = rsqrtf(h * h + 4.0f * apq * apq + 1e-38f);
    float sgn = copysignf(1.0f, h);
    float cos2t = fminf(fabsf(h) * w, 1.0f);
    float sin2t = 2.0f * apq * w * sgn;
    float c2 = 0.5f * (1.0f + cos2t);
    float invc = rsqrtf(c2);
    float c = c2 * invc;
    float s = 0.5f * sin2t * invc;
    int r = 3 - p - q;
    float arp = A[r][p], arq = A[r][q];
    float narp = c * arp - s * arq;
    float narq = s * arp + c * arq;
    A[r][p] = narp; A[p][r] = narp;
    A[r][q] = narq; A[q][r] = narq;
    float napp = c * c * app - 2.0f * s * c * apq + s * s * aqq;
    float naqq = s * s * app + 2.0f * s * c * apq + c * c * aqq;
    A[p][p] = napp; A[q][q] = naqq;
    A[p][q] = 0.0f; A[q][p] = 0.0f;
#pragma unroll
    for (int i = 0; i < 3; i++) {
        float vip = V[i][p], viq = V[i][q];
        V[i][p] = c * vip - s * viq;
        V[i][q] = s * vip + c * viq;
    }
}

// Full Procrustes solve + mean per-joint error for one element held in registers.
__device__ __forceinline__ float solve_element(const float pf[EF], const float gf[EF]) {
    const float invJ = 1.0f / (float)NJ;

    float mu1[3] = {0.f, 0.f, 0.f};
    float mu2[3] = {0.f, 0.f, 0.f};
#pragma unroll
    for (int j = 0; j < NJ; j++)
#pragma unroll
        for (int a = 0; a < 3; a++) {
            mu1[a] += pf[j * 3 + a];
            mu2[a] += gf[j * 3 + a];
        }
#pragma unroll
    for (int a = 0; a < 3; a++) { mu1[a] *= invJ; mu2[a] *= invJ; }

    float K[3][3] = {{0}};
    float var1 = 0.f;
#pragma unroll
    for (int j = 0; j < NJ; j++) {
        float x[3], y[3];
#pragma unroll
        for (int a = 0; a < 3; a++) {
            x[a] = pf[j * 3 + a] - mu1[a];
            y[a] = gf[j * 3 + a] - mu2[a];
            var1 += x[a] * x[a];
        }
#pragma unroll
        for (int a = 0; a < 3; a++)
#pragma unroll
            for (int b = 0; b < 3; b++)
                K[a][b] += x[a] * y[b];
    }

    float A[3][3];
#pragma unroll
    for (int i = 0; i < 3; i++)
#pragma unroll
        for (int j = i; j < 3; j++) {
            float acc = 0.f;
#pragma unroll
            for (int k = 0; k < 3; k++) acc += K[k][i] * K[k][j];
            A[i][j] = acc; A[j][i] = acc;
        }

    float V[3][3] = {{1.f, 0.f, 0.f}, {0.f, 1.f, 0.f}, {0.f, 0.f, 1.f}};
#pragma unroll
    for (int sweep = 0; sweep < 2; sweep++) {
        jacobi_rot(A, V, 0, 1);
        jacobi_rot(A, V, 0, 2);
        jacobi_rot(A, V, 1, 2);
    }
    jacobi_rot(A, V, 0, 1);

    float lam[3] = {A[0][0], A[1][1], A[2][2]};
#pragma unroll
    for (int a = 0; a < 2; a++)
#pragma unroll
        for (int b = a + 1; b < 3; b++)
            if (lam[a] < lam[b]) {
                float tl = lam[a]; lam[a] = lam[b]; lam[b] = tl;
#pragma unroll
                for (int r = 0; r < 3; r++) {
                    float tv = V[r][a]; V[r][a] = V[r][b]; V[r][b] = tv;
                }
            }

    float v0[3] = {V[0][0], V[1][0], V[2][0]};
    float v1[3] = {V[0][1], V[1][1], V[2][1]};
    float v2[3] = {v0[1]*v1[2] - v0[2]*v1[1],
                   v0[2]*v1[0] - v0[0]*v1[2],
                   v0[0]*v1[1] - v0[1]*v1[0]};

    float u0[3], u1[3];
#pragma unroll
    for (int i = 0; i < 3; i++) {
        u0[i] = K[i][0]*v0[0] + K[i][1]*v0[1] + K[i][2]*v0[2];
        u1[i] = K[i][0]*v1[0] + K[i][1]*v1[1] + K[i][2]*v1[2];
    }
    float n0 = rsqrtf(u0[0]*u0[0] + u0[1]*u0[1] + u0[2]*u0[2] + 1e-30f);
#pragma unroll
    for (int i = 0; i < 3; i++) u0[i] *= n0;
    float dot01 = u0[0]*u1[0] + u0[1]*u1[1] + u0[2]*u1[2];
#pragma unroll
    for (int i = 0; i < 3; i++) u1[i] -= dot01 * u0[i];
    float n1 = rsqrtf(u1[0]*u1[0] + u1[1]*u1[1] + u1[2]*u1[2] + 1e-30f);
#pragma unroll
    for (int i = 0; i < 3; i++) u1[i] *= n1;
    float u2[3] = {u0[1]*u1[2] - u0[2]*u1[1],
                   u0[2]*u1[0] - u0[0]*u1[2],
                   u0[0]*u1[1] - u0[1]*u1[0]};

    float R[3][3];
#pragma unroll
    for (int i = 0; i < 3; i++)
#pragma unroll
        for (int j = 0; j < 3; j++)
            R[i][j] = v0[i]*u0[j] + v1[i]*u1[j] + v2[i]*u2[j];

    float trRK = 0.f;
#pragma unroll
    for (int i = 0; i < 3; i++)
#pragma unroll
        for (int k = 0; k < 3; k++)
            trRK += R[i][k] * K[k][i];
    float scale = __fdividef(trRK, var1 + 1e-30f);

    float acc = 0.f;
#pragma unroll
    for (int j = 0; j < NJ; j++) {
        float x[3], y[3];
#pragma unroll
        for (int a = 0; a < 3; a++) {
            x[a] = pf[j * 3 + a] - mu1[a];
            y[a] = gf[j * 3 + a] - mu2[a];
        }
        float d0 = scale * (R[0][0]*x[0] + R[0][1]*x[1] + R[0][2]*x[2]) - y[0];
        float d1 = scale * (R[1][0]*x[0] + R[1][1]*x[1] + R[1][2]*x[2]) - y[1];
        float d2 = scale * (R[2][0]*x[0] + R[2][1]*x[1] + R[2][2]*x[2]) - y[2];
        acc += fast_sqrt(d0*d0 + d1*d1 + d2*d2);
    }
    return acc * invJ;
}

// Prefetch a full tile (32 elements, both tensors) into one warp buffer.
__device__ __forceinline__ void prefetch_tile(const float* __restrict__ pred,
                                              const float* __restrict__ gt,
                                              int tile, uint32_t pbyte, int lane) {
    const float4* __restrict__ ps = (const float4*)(pred + (size_t)tile * TILE_F);
    const float4* __restrict__ gs = (const float4*)(gt   + (size_t)tile * TILE_F);
    uint32_t gbyte = pbyte + TILE_F * 4;
#pragma unroll
    for (int i = 0; i < 11; i++) {
        int idx = lane + i * 32;
        if (idx < TILE_F4) {
            cp16(pbyte + idx * 16, ps + idx);
            cp16(gbyte + idx * 16, gs + idx);
        }
    }
}

__global__ void __launch_bounds__(TPB)
pampjpe_kernel(const float* __restrict__ pred,
               const float* __restrict__ gt,
               float* __restrict__ out, int B)
{
    extern __shared__ float smem[];   // WARPS * 2 * BUF_F floats = 86016 bytes

    const int lane = threadIdx.x & 31;
    const int wid  = threadIdx.x >> 5;
    const int warp_gid = blockIdx.x * WARPS + wid;
    const int nwarps   = GRID * WARPS;
    const int NT = (B + TILE - 1) / TILE;  // total tiles
    const int NF = B / TILE;               // full tiles

    float* buf0c = smem + (wid * 2 + 0) * BUF_F;
    float* buf1c = smem + (wid * 2 + 1) * BUF_F;
    uint32_t bufb[2] = { smem_u32(buf0c), smem_u32(buf1c) };
    float*   bufc[2] = { buf0c, buf1c };

    int t = warp_gid;
    if (t < NF) prefetch_tile(pred, gt, t, bufb[0], lane);
    asm volatile("cp.async.commit_group;\n" ::: "memory");

    int ib = 0;
    for (; t < NT; t += nwarps, ib ^= 1) {
        int nxt = t + nwarps;
        if (nxt < NF) prefetch_tile(pred, gt, nxt, bufb[ib ^ 1], lane);
        asm volatile("cp.async.commit_group;\n" ::: "memory");
        asm volatile("cp.async.wait_group 1;\n" ::: "memory");
        __syncwarp();

        float pf[EF], gf[EF];
        int e = t * TILE + lane;
        if (t < NF) {
            // Conflict-free float2 reads: 16 lanes/phase, gcd(21,16)=1.
            const float2* __restrict__ p2 = (const float2*)(bufc[ib]) + lane * (EF / 2);
            const float2* __restrict__ g2 = (const float2*)(bufc[ib] + TILE_F) + lane * (EF / 2);
#pragma unroll
            for (int j = 0; j < EF / 2; j++) {
                float2 a = p2[j]; pf[2*j] = a.x; pf[2*j+1] = a.y;
                float2 b = g2[j]; gf[2*j] = b.x; gf[2*j+1] = b.y;
            }
        } else {
            // Partial tail tile: direct (guarded) global loads.
#pragma unroll
            for (int k = 0; k < EF; k++) { pf[k] = 0.f; gf[k] = 0.f; }
            if (e < B) {
                const float* pp = pred + (size_t)e * EF;
                const float* gg = gt   + (size_t)e * EF;
#pragma unroll
                for (int k = 0; k < EF; k++) { pf[k] = pp[k]; gf[k] = gg[k]; }
            }
        }

        float result = solve_element(pf, gf);
        if (e < B) out[e] = result;
        __syncwarp();   // all lanes done reading buf[ib^1]'s predecessor before reuse
    }
}

extern "C" void kernel_launch(void* const* d_in, const int* in_sizes, int n_in,
                              void* d_out, int out_size) {
    const float* pred = (const float*)d_in[0];
    const float* gt   = (const float*)d_in[1];
    float* out = (float*)d_out;
    int B = in_sizes[0] / EF;

    static const size_t smem_bytes = (size_t)WARPS * 2 * BUF_F * sizeof(float); // 86016
    cudaFuncSetAttribute(pampjpe_kernel,
                         cudaFuncAttributeMaxDynamicSharedMemorySize,
                         (int)smem_bytes);
    pampjpe_kernel<<<GRID, TPB, smem_bytes>>>(pred, gt, out, B);
}